// round 7
// baseline (speedup 1.0000x reference)
#include <cuda_runtime.h>

// Problem constants (fixed by the reference module)
#define N_  16
#define D_  3
#define H_  160
#define W_  160
#define M_  8
#define K_  10
#define P_  15
#define PM_ 7               // (P-1)/2
#define OH_ (H_ - P_ + 1)   // 146
#define OW_ (W_ - P_ + 1)   // 146
#define MK_ (M_ * K_)       // 80
#define PLANE_ (OH_ * OW_)  // 21316

// Block = (n, k, row-group). All 8 m-values for a given k share the same
// (n, channels[k]) input plane -> stage it in smem once, 8x reuse.
// Row group: 32 output rows; smem holds 46 input rows (sy in [0,12], +1 tap,
// +32 rows). 5 row groups (last clamped to y0=114). Warp m sweeps 5 column
// bands of 32 cols (last clamped to x0=114); overlaps write identical values.
#define HTILE_ 32
#define RG_    5
#define SROWS_ 46
#define NBLOCKS_ (N_ * K_ * RG_)   // 800

__global__ __launch_bounds__(256, 6)
void fern_bits_kernel(
    const float* __restrict__ T,
    const float* __restrict__ dx1, const float* __restrict__ dx2,
    const float* __restrict__ dy1, const float* __restrict__ dy2,
    const float* __restrict__ th,  const float* __restrict__ amb,
    const int*   __restrict__ channels,
    float* __restrict__ out)
{
    __shared__ float splane[SROWS_ * W_];   // 46*160*4 = 29440 B

    // ---- block decode: bid = (n*K + k)*RG + rg ----
    const int bid = blockIdx.x;
    const int rg  = bid % RG_;
    const int nk  = bid / RG_;
    const int k   = nk % K_;
    const int n   = nk / K_;
    const int ch  = channels[k];

    const int y0 = min(rg * HTILE_, OH_ - HTILE_);   // 0,32,64,96,114
    const int row_base = y0;                          // smem row 0 = plane row y0
    // smem covers plane rows [y0, y0+45]; max = 114+45 = 159 < 160. OK.

    // ---- cooperative plane staging: linear float4 copy ----
    const float* __restrict__ img = T + ((size_t)(n * D_ + ch)) * (H_ * W_);
    {
        const float4* __restrict__ g4 = (const float4*)(img + row_base * W_);
        float4* s4 = (float4*)splane;
        #pragma unroll
        for (int i = threadIdx.x; i < (SROWS_ * W_) / 4; i += 256)
            s4[i] = g4[i];
    }
    __syncthreads();

    // ---- per-warp: one m value ----
    const int m    = threadIdx.x >> 5;
    const int lane = threadIdx.x & 31;
    const int mk   = m * K_ + k;
    const int nmk  = n * MK_ + mk;

    // per-(m,k) parameters (uniform per warp, broadcast loads)
    const float a1x = dx1[mk], a2x = dx2[mk];
    const float a1y = dy1[mk], a2y = dy2[mk];
    const float fl1x = floorf(a1x), fl2x = floorf(a2x);
    const float fl1y = floorf(a1y), fl2y = floorf(a2y);
    const float f1x = a1x - fl1x, f2x = a2x - fl2x;
    const float f1y = a1y - fl1y, f2y = a2y - fl2y;
    const float g1x = 1.0f - f1x, g2x = 1.0f - f2x;
    const float g1y  = 1.0f - f1y;
    const float ng2y = -(1.0f - f2y), nf2y = -f2y;
    const int sx1 = PM_ + (int)fl1x, sx2 = PM_ + (int)fl2x;
    const int sy1 = PM_ + (int)fl1y, sy2 = PM_ + (int)fl2y;

    const float thv = th[mk];
    const float pos = amb[(m * 2 + 0) * K_ + k];
    const float neg = amb[(m * 2 + 1) * K_ + k];
    const float inv = 1.0f / (pos - neg + 1e-29f);
    const float c   = -(thv + neg) * inv;   // v = sat(temp*inv + c)

    // ---- sweep 5 column bands (rolled loop; inner rows fully unrolled) ----
    for (int cb = 0; cb < 5; cb++) {
        const int x0 = min(cb * 32, OW_ - 32);   // 0,32,64,96,114
        const int x  = x0 + lane;

        // smem tap bases (sx in [0,12], x <= 145 -> col <= 158 < 160)
        const float* s1 = splane + sy1 * W_ + sx1 + x;
        const float* s2 = splane + sy2 * W_ + sx2 + x;
        float* op = out + (size_t)nmk * PLANE_ + y0 * OW_ + x;

        // prologue: horizontal lerp of strip input row 0
        float prev1 = g1x * s1[0] + f1x * s1[1];
        float prev2 = g2x * s2[0] + f2x * s2[1];

        #pragma unroll
        for (int r = 1; r <= HTILE_; r++) {
            const float a0 = s1[r * W_], a1 = s1[r * W_ + 1];
            const float b0 = s2[r * W_], b1 = s2[r * W_ + 1];
            const float cur1 = g1x * a0 + f1x * a1;
            const float cur2 = g2x * b0 + f2x * b1;

            float temp = g1y * prev1;
            temp = fmaf(f1y,  cur1,  temp);
            temp = fmaf(ng2y, prev2, temp);
            temp = fmaf(nf2y, cur2,  temp);
            prev1 = cur1;
            prev2 = cur2;

            if (fabsf(temp) < 1e-5f) temp = 0.0f;
            op[(r - 1) * OW_] = __saturatef(fmaf(temp, inv, c));
        }
    }
}

extern "C" void kernel_launch(void* const* d_in, const int* in_sizes, int n_in,
                              void* d_out, int out_size)
{
    const float* T        = (const float*)d_in[0];
    const float* dx1      = (const float*)d_in[1];
    const float* dx2      = (const float*)d_in[2];
    const float* dy1      = (const float*)d_in[3];
    const float* dy2      = (const float*)d_in[4];
    const float* th       = (const float*)d_in[5];
    const float* amb      = (const float*)d_in[6];
    const int*   channels = (const int*)  d_in[7];
    float* out = (float*)d_out;

    fern_bits_kernel<<<NBLOCKS_, 256>>>(
        T, dx1, dx2, dy1, dy2, th, amb, channels, out);
}